// round 4
// baseline (speedup 1.0000x reference)
#include <cuda_runtime.h>
#include <stdint.h>

// ---------------------------------------------------------------------------
// W4A8 per-group GEMM (legacy IMMA path — tcgen05 unavailable: harness builds
// .target sm_103 PTX which rejects tcgen05).
//   w_int8[o,k] = q4[o,k]*s2[g,o] + z[g,o]   (exact in int8, |w|<=105)
//   acc[m,o]    = sum_k x_i8[m,k]*w_int8[o,k]  (s32, mma.m16n8k32)
//   out[m,o]    = acc * isc[m] * s1[o] + bias[o]
//
// cp.async.cg half-group pipeline (no register staging), dequant smem->smem,
// A fragments LDG'd from L2-hot packed x, 3 CTAs/SM (all 224 CTAs resident).
// Round-4 fix: A-row stride in WORDS (1024), was 32 (int4 habit) -> rel_err 1.38.
// ---------------------------------------------------------------------------

#define M_DIM 64
#define K_DIM 4096
#define N_DIM 14336
#define G_DIM 32
#define NT    64           // output channels per CTA -> 224 CTAs
#define BROW  144          // padded smem row for dequant tile (conflict-free)

#define CP_ASYNC16(dst, src) \
    asm volatile("cp.async.cg.shared.global [%0], [%1], 16;\n" :: "r"(dst), "l"(src))
#define CP_COMMIT()  asm volatile("cp.async.commit_group;\n")
#define CP_WAIT(N)   asm volatile("cp.async.wait_group %0;\n" :: "n"(N))

__device__ __forceinline__ unsigned smem_u32(const void* p) {
    unsigned a;
    asm("{ .reg .u64 t; cvta.to.shared.u64 t, %1; cvt.u32.u64 %0, t; }" : "=r"(a) : "l"(p));
    return a;
}

// int8-packed activations [M][K] (256 KB static scratch)
__device__ __align__(16) unsigned int g_x_packed[M_DIM * K_DIM / 4];

// ---- pass 0: pack x int32 -> int8 -------------------------------------------
__global__ void pack_x_kernel(const int* __restrict__ x) {
    int idx = blockIdx.x * blockDim.x + threadIdx.x;   // one packed word
    if (idx >= M_DIM * K_DIM / 4) return;
    const int4 v = reinterpret_cast<const int4*>(x)[idx];
    unsigned a = __byte_perm((unsigned)v.x, (unsigned)v.y, 0x0040);
    unsigned b = __byte_perm((unsigned)v.z, (unsigned)v.w, 0x0040);
    g_x_packed[idx] = __byte_perm(a, b, 0x5410);
}

// ---- main GEMM ---------------------------------------------------------------
__global__ __launch_bounds__(256, 3)
void w4a8_gemm_kernel(const int*   __restrict__ qw,    // [N,K] int32 (0..15)
                      const int*   __restrict__ s2s,   // [G,N]
                      const int*   __restrict__ s2z,   // [G,N]
                      const float* __restrict__ isc,   // [M]
                      const float* __restrict__ s1,    // [N]
                      const float* __restrict__ bias,  // [N]
                      float*       __restrict__ out)   // [M,N]
{
    // raw weight staging: 2 half-group stages x 16KB (64 rows x 64 ints)
    __shared__ __align__(16) uint4 sRaw[2][1024];
    // dequantized s8 weight tile: 64 rows x 128B (padded)
    __shared__ __align__(16) unsigned char sB[NT * BROW];

    const int tid = threadIdx.x;
    const int n0  = blockIdx.x * NT;

    // producer mapping: thread -> (weight row 0..63, 16-int segment 0..3)
    const int row = tid >> 2;
    const int seg = tid & 3;
    // stage s covers k-ints [s*64, s*64+64) of each row; thread owns 16 ints.
    const char* gsrc0 = reinterpret_cast<const char*>(
        qw + (size_t)(n0 + row) * K_DIM + seg * 16);
    // smem chunk layout (16B units): chunk(t,j) = (t>>3)*32 + (t&7) + 8*j
    // -> conflict-free phases, each thread reads back only its own chunks.
    const unsigned rawBase  = smem_u32(&sRaw[0][0]);
    const unsigned myChunk0 = ((unsigned)(tid >> 3) * 32u + (unsigned)(tid & 7)) * 16u;

    // MMA mapping: 8 warps as 4(M) x 2(N); warp tile 16m x 32n
    const int warp = tid >> 5, lane = tid & 31;
    const int wm = warp >> 1;
    const int wn = warp & 1;
    const int g4 = lane >> 2, tg = lane & 3;

    // A fragment gmem WORD indices (row stride = K_DIM/4 = 1024 words)
    const unsigned* xw = g_x_packed;
    const int arow0 = (wm * 16 + g4) * (K_DIM / 4);
    const int arow1 = (wm * 16 + g4 + 8) * (K_DIM / 4);

    int acc[4][4];
#pragma unroll
    for (int i = 0; i < 4; i++)
#pragma unroll
        for (int j = 0; j < 4; j++) acc[i][j] = 0;

    // ---- prologue: issue stages 0 and 1 ----
#pragma unroll
    for (int s = 0; s < 2; s++) {
        const unsigned dst = rawBase + s * 16384u + myChunk0;
        const char* src = gsrc0 + (size_t)s * 256;
#pragma unroll
        for (int j = 0; j < 4; j++) CP_ASYNC16(dst + j * 128u, src + j * 16);
        CP_COMMIT();
    }

    int s2v = s2s[n0 + row];
    int zv  = s2z[n0 + row];

    for (int g = 0; g < G_DIM; ++g) {
        // ---- consume two half-group stages: dequant raw -> sB ----
#pragma unroll
        for (int h = 0; h < 2; h++) {
            const int s = 2 * g + h;
            if (s == 2 * G_DIM - 1) { CP_WAIT(0); } else { CP_WAIT(1); }

            const unsigned roff = (unsigned)(s & 1) * 16384u + myChunk0;
            unsigned pk[4];
#pragma unroll
            for (int j = 0; j < 4; j++) {
                int4 q = *reinterpret_cast<const int4*>(
                    reinterpret_cast<const char*>(sRaw) + roff + j * 128u);
                int w0 = q.x * s2v + zv;
                int w1 = q.y * s2v + zv;
                int w2 = q.z * s2v + zv;
                int w3 = q.w * s2v + zv;
                pk[j] = __byte_perm(__byte_perm((unsigned)w0, (unsigned)w1, 0x0040),
                                    __byte_perm((unsigned)w2, (unsigned)w3, 0x0040), 0x5410);
            }
            // refill this stage's buffer with stage s+2 (own chunks only; the
            // async write lands hundreds of cycles after the LDS above issued)
            if (s + 2 < 2 * G_DIM) {
                const unsigned dst = rawBase + roff;
                const char* src = gsrc0 + (size_t)(s + 2) * 256;
#pragma unroll
                for (int j = 0; j < 4; j++) CP_ASYNC16(dst + j * 128u, src + j * 16);
                CP_COMMIT();
            }
            *reinterpret_cast<uint4*>(&sB[row * BROW + h * 64 + seg * 16]) =
                make_uint4(pk[0], pk[1], pk[2], pk[3]);
        }

        // prefetch next group's scales (tiny, L2-hot)
        int s2n = 0, zn = 0;
        if (g + 1 < G_DIM) {
            s2n = s2s[(g + 1) * N_DIM + n0 + row];
            zn  = s2z[(g + 1) * N_DIM + n0 + row];
        }

        __syncthreads();   // sB tile complete

        // ---- MMA over this K=128 chunk: 4 k32-steps x 4 n8-subtiles ----
        const int kw = g * 32;   // word offset of this group in a packed-x row
#pragma unroll
        for (int ks = 0; ks < 4; ks++) {
            unsigned a0 = xw[arow0 + kw + ks * 8 + tg];
            unsigned a1 = xw[arow1 + kw + ks * 8 + tg];
            unsigned a2 = xw[arow0 + kw + ks * 8 + tg + 4];
            unsigned a3 = xw[arow1 + kw + ks * 8 + tg + 4];
#pragma unroll
            for (int ns = 0; ns < 4; ns++) {
                const unsigned char* bp = sB + (wn * 32 + ns * 8 + g4) * BROW + ks * 32 + tg * 4;
                unsigned b0 = *(const unsigned*)(bp);
                unsigned b1 = *(const unsigned*)(bp + 16);
                asm volatile(
                    "mma.sync.aligned.m16n8k32.row.col.s32.s8.s8.s32 "
                    "{%0,%1,%2,%3}, {%4,%5,%6,%7}, {%8,%9}, {%0,%1,%2,%3};\n"
                    : "+r"(acc[ns][0]), "+r"(acc[ns][1]),
                      "+r"(acc[ns][2]), "+r"(acc[ns][3])
                    : "r"(a0), "r"(a1), "r"(a2), "r"(a3), "r"(b0), "r"(b1));
            }
        }

        __syncthreads();   // all warps done reading sB before next stores

        s2v = s2n; zv = zn;
    }

    // ---- epilogue: out = acc * isc[m] * s1[n] + bias[n] ----
    const int m0 = wm * 16 + g4;
    const float isc0 = isc[m0];
    const float isc1 = isc[m0 + 8];
#pragma unroll
    for (int ns = 0; ns < 4; ns++) {
        const int n = n0 + wn * 32 + ns * 8 + tg * 2;
        const float s1a = s1[n],   s1b = s1[n + 1];
        const float ba  = bias[n], bb  = bias[n + 1];
        out[ m0      * N_DIM + n    ] = (float)acc[ns][0] * isc0 * s1a + ba;
        out[ m0      * N_DIM + n + 1] = (float)acc[ns][1] * isc0 * s1b + bb;
        out[(m0 + 8) * N_DIM + n    ] = (float)acc[ns][2] * isc1 * s1a + ba;
        out[(m0 + 8) * N_DIM + n + 1] = (float)acc[ns][3] * isc1 * s1b + bb;
    }
}

// ---------------------------------------------------------------------------
extern "C" void kernel_launch(void* const* d_in, const int* in_sizes, int n_in,
                              void* d_out, int out_size) {
    const int*   x    = (const int*)  d_in[0];  // [M,K] int32 (int8 values)
    const float* isc  = (const float*)d_in[1];  // [M]
    // d_in[2] = input_sum (unused)
    const int*   qw   = (const int*)  d_in[3];  // [N,K] int32 (uint4 values)
    const int*   s2s  = (const int*)  d_in[4];  // [G,N]
    const int*   s2z  = (const int*)  d_in[5];  // [G,N]
    const float* s1   = (const float*)d_in[6];  // [N]
    const float* bias = (const float*)d_in[7];  // [N]
    float* out = (float*)d_out;

    pack_x_kernel<<<(M_DIM * K_DIM / 4 + 255) / 256, 256>>>(x);
    w4a8_gemm_kernel<<<N_DIM / NT, 256>>>(qw, s2s, s2z, isc, s1, bias, out);
}

// round 5
// speedup vs baseline: 1.6198x; 1.6198x over previous
#include <cuda_runtime.h>
#include <stdint.h>

// ---------------------------------------------------------------------------
// W4A8 per-group GEMM, legacy IMMA (tcgen05 rejected by sm_103 PTX target).
//   w_int8[o,k] = q4[o,k]*s2[g,o] + z[g,o]   (exact int8, |w| <= 105)
//   acc[m,o]    = sum_k x_i8[m,k]*w_int8[o,k]  (s32 mma.m16n8k32)
//   out[m,o]    = acc * isc[m] * s1[o] + bias[o]
//
// Round 5: round-1 structure (register prefetch, double-buffered smem,
// 1 sync/group) but 512 threads/CTA. Grid is fixed at 224 CTAs (1.51/SM),
// so warps/CTA is the only occupancy lever: 16 warps/CTA -> ~24 warps/SM.
// ---------------------------------------------------------------------------

#define M_DIM 64
#define K_DIM 4096
#define N_DIM 14336
#define G_DIM 32
#define GS    128          // K per group
#define NT    64           // output channels per CTA -> 224 CTAs
#define BROW  (GS + 16)    // padded smem row (144B), conflict-free phases
#define THREADS 512

// int8-packed activations [M][K] (256 KB static scratch)
__device__ __align__(16) unsigned int g_x_packed[M_DIM * K_DIM / 4];

// ---- pass 0: pack x int32 -> int8 -------------------------------------------
__global__ void pack_x_kernel(const int* __restrict__ x) {
    int idx = blockIdx.x * blockDim.x + threadIdx.x;   // one packed word
    if (idx >= M_DIM * K_DIM / 4) return;
    const int4 v = reinterpret_cast<const int4*>(x)[idx];
    unsigned a = __byte_perm((unsigned)v.x, (unsigned)v.y, 0x0040);
    unsigned b = __byte_perm((unsigned)v.z, (unsigned)v.w, 0x0040);
    g_x_packed[idx] = __byte_perm(a, b, 0x5410);
}

// ---- main GEMM ---------------------------------------------------------------
__global__ __launch_bounds__(THREADS, 2)
void w4a8_gemm_kernel(const int*   __restrict__ qw,    // [N,K] int32 (0..15)
                      const int*   __restrict__ s2s,   // [G,N]
                      const int*   __restrict__ s2z,   // [G,N]
                      const float* __restrict__ isc,   // [M]
                      const float* __restrict__ s1,    // [N]
                      const float* __restrict__ bias,  // [N]
                      float*       __restrict__ out)   // [M,N]
{
    __shared__ __align__(16) unsigned char sA[2][M_DIM * BROW]; // x tile 64x128 s8
    __shared__ __align__(16) unsigned char sB[2][NT * BROW];    // w tile 64x128 s8

    const int tid = threadIdx.x;
    const int n0  = blockIdx.x * NT;

    // B dequant mapping: thread -> (weight row 0..63, 16-int segment 0..7)
    const int brow = tid >> 3;              // 0..63
    const int bseg = tid & 7;               // 0..7
    const int4* qbase = reinterpret_cast<const int4*>(qw)
                      + (size_t)(n0 + brow) * (K_DIM / 4) + bseg * 4;

    // A mapping: thread -> one int4 (row 0..63, 16B chunk 0..7)
    const int xrow = tid >> 3, xoff = tid & 7;
    const int4* xbase = reinterpret_cast<const int4*>(g_x_packed)
                      + xrow * (K_DIM / 16) + xoff;

    // MMA mapping: 16 warps as 4(M) x 4(N); warp tile 16m x 16n
    const int warp = tid >> 5, lane = tid & 31;
    const int wm = warp >> 2;               // 0..3
    const int wn = warp & 3;                // 0..3
    const int g4 = lane >> 2, tg = lane & 3;

    int acc[2][4];
#pragma unroll
    for (int i = 0; i < 2; i++)
#pragma unroll
        for (int j = 0; j < 4; j++) acc[i][j] = 0;

    int4 qr[4], qn[4];   // 16 raw qweight ints (this thread's slice)
    int4 xr, xn;
    int  s2v, zv, s2n, zn;

    // prefetch group 0
#pragma unroll
    for (int j = 0; j < 4; j++) qr[j] = qbase[j];
    xr  = xbase[0];
    s2v = s2s[n0 + brow];
    zv  = s2z[n0 + brow];

    for (int g = 0; g < G_DIM; ++g) {
        const int buf = g & 1;

        // ---- dequant 16 weights -> s8, store 16B into sB ----
        unsigned pk[4];
#pragma unroll
        for (int j = 0; j < 4; j++) {
            int w0 = qr[j].x * s2v + zv;
            int w1 = qr[j].y * s2v + zv;
            int w2 = qr[j].z * s2v + zv;
            int w3 = qr[j].w * s2v + zv;
            pk[j] = __byte_perm(__byte_perm((unsigned)w0, (unsigned)w1, 0x0040),
                                __byte_perm((unsigned)w2, (unsigned)w3, 0x0040), 0x5410);
        }
        *reinterpret_cast<uint4*>(&sB[buf][brow * BROW + bseg * 16]) =
            make_uint4(pk[0], pk[1], pk[2], pk[3]);
        // ---- store A tile (16B per thread) ----
        *reinterpret_cast<int4*>(&sA[buf][xrow * BROW + xoff * 16]) = xr;

        // ---- prefetch next group into registers (covered by MMA phase) ----
        if (g + 1 < G_DIM) {
            const int4* qp = qbase + (g + 1) * (GS / 4);
#pragma unroll
            for (int j = 0; j < 4; j++) qn[j] = qp[j];
            xn  = xbase[(g + 1) * (GS / 16)];
            s2n = s2s[(g + 1) * N_DIM + n0 + brow];
            zn  = s2z[(g + 1) * N_DIM + n0 + brow];
        }

        __syncthreads();   // tile (buf) complete; double buffer => 1 sync/iter

        // ---- MMA over this K=128 chunk: 4 k32-steps x 2 n8-subtiles ----
        const unsigned char* aBase = sA[buf];
        const unsigned char* bBase = sB[buf];
#pragma unroll
        for (int ks = 0; ks < 4; ks++) {
            unsigned a0 = *(const unsigned*)(aBase + (wm*16 + g4    ) * BROW + ks*32 + tg*4);
            unsigned a1 = *(const unsigned*)(aBase + (wm*16 + g4 + 8) * BROW + ks*32 + tg*4);
            unsigned a2 = *(const unsigned*)(aBase + (wm*16 + g4    ) * BROW + ks*32 + tg*4 + 16);
            unsigned a3 = *(const unsigned*)(aBase + (wm*16 + g4 + 8) * BROW + ks*32 + tg*4 + 16);
#pragma unroll
            for (int ns = 0; ns < 2; ns++) {
                const unsigned char* bp = bBase + (wn*16 + ns*8 + g4) * BROW + ks*32 + tg*4;
                unsigned b0 = *(const unsigned*)(bp);
                unsigned b1 = *(const unsigned*)(bp + 16);
                asm volatile(
                    "mma.sync.aligned.m16n8k32.row.col.s32.s8.s8.s32 "
                    "{%0,%1,%2,%3}, {%4,%5,%6,%7}, {%8,%9}, {%0,%1,%2,%3};\n"
                    : "+r"(acc[ns][0]), "+r"(acc[ns][1]),
                      "+r"(acc[ns][2]), "+r"(acc[ns][3])
                    : "r"(a0), "r"(a1), "r"(a2), "r"(a3), "r"(b0), "r"(b1));
            }
        }

        // rotate prefetch registers
#pragma unroll
        for (int j = 0; j < 4; j++) qr[j] = qn[j];
        xr = xn; s2v = s2n; zv = zn;
    }

    // ---- epilogue: out = acc * isc[m] * s1[n] + bias[n] ----
    const int m0 = wm * 16 + g4;
    const float isc0 = isc[m0];
    const float isc1 = isc[m0 + 8];
#pragma unroll
    for (int ns = 0; ns < 2; ns++) {
        const int n = n0 + wn * 16 + ns * 8 + tg * 2;
        const float s1a = s1[n],   s1b = s1[n + 1];
        const float ba  = bias[n], bb  = bias[n + 1];
        out[ m0      * N_DIM + n    ] = (float)acc[ns][0] * isc0 * s1a + ba;
        out[ m0      * N_DIM + n + 1] = (float)acc[ns][1] * isc0 * s1b + bb;
        out[(m0 + 8) * N_DIM + n    ] = (float)acc[ns][2] * isc1 * s1a + ba;
        out[(m0 + 8) * N_DIM + n + 1] = (float)acc[ns][3] * isc1 * s1b + bb;
    }
}

// ---------------------------------------------------------------------------
extern "C" void kernel_launch(void* const* d_in, const int* in_sizes, int n_in,
                              void* d_out, int out_size) {
    const int*   x    = (const int*)  d_in[0];  // [M,K] int32 (int8 values)
    const float* isc  = (const float*)d_in[1];  // [M]
    // d_in[2] = input_sum (unused)
    const int*   qw   = (const int*)  d_in[3];  // [N,K] int32 (uint4 values)
    const int*   s2s  = (const int*)  d_in[4];  // [G,N]
    const int*   s2z  = (const int*)  d_in[5];  // [G,N]
    const float* s1   = (const float*)d_in[6];  // [N]
    const float* bias = (const float*)d_in[7];  // [N]
    float* out = (float*)d_out;

    pack_x_kernel<<<(M_DIM * K_DIM / 4 + 255) / 256, 256>>>(x);
    w4a8_gemm_kernel<<<N_DIM / NT, THREADS>>>(qw, s2s, s2z, isc, s1, bias, out);
}